// round 12
// baseline (speedup 1.0000x reference)
#include <cuda_runtime.h>
#include <math.h>

#define BATCH   256
#define NPTS    20000
#define TSTEPS  10
#define LAT     10
#define BPB     5              // integrate blocks per batch
#define PPB     (NPTS / BPB)   // 4000 points per block
#define ITHREADS 512
#define COEF_PER_BATCH (TSTEPS * 256 * 8)   // 20480 floats = 80 KB
#define HALF_COEF (COEF_PER_BATCH / 2)      // 10240 floats = 40 KB
#define NSBLK   40             // sort blocks: 40*512 >= NPTS

// ---- device scratch (no allocations allowed) ----
__device__ float  g_coef[BATCH * COEF_PER_BATCH];   // [b][t][cell(16x16)][8]
__device__ float  g_a4[BATCH * 256];                // encoder layer-4 activations
__device__ int    g_order[NPTS];
__device__ float2 g_tps[NPTS];
__device__ int    g_bhist[NSBLK][256];
__device__ int    g_bbase[NSBLK][256];

__device__ __forceinline__ float tanh_fast(float x) {
    float y;
    asm("tanh.approx.f32 %0, %1;" : "=f"(y) : "f"(x));
    return y;
}

__device__ __forceinline__ int cell_of(float2 P) {
    int ui = min(max(__float2int_rd((P.x + 2.5f) * 3.0f), 0), 15);
    int vi = min(max(__float2int_rd((P.y + 2.5f) * 3.0f), 0), 15);
    return ui * 16 + vi;
}

// ============================================================================
// Counting sort by initial grid cell — 3 kernels, NO global atomics.
// ============================================================================
__global__ void sort_count_kernel(const float* __restrict__ tpl)
{
    __shared__ int lh[256];
    const int tid = threadIdx.x;
    if (tid < 256) lh[tid] = 0;
    __syncthreads();
    int p = blockIdx.x * 512 + tid;
    if (p < NPTS) atomicAdd(&lh[cell_of(((const float2*)tpl)[p])], 1);
    __syncthreads();
    if (tid < 256) g_bhist[blockIdx.x][tid] = lh[tid];
}

__global__ void sort_scan_kernel()
{
    __shared__ int tmp[256];
    const int c = threadIdx.x;
    int total = 0;
    #pragma unroll
    for (int bk = 0; bk < NSBLK; bk++) total += g_bhist[bk][c];
    tmp[c] = total;
    __syncthreads();
    #pragma unroll
    for (int off = 1; off < 256; off <<= 1) {
        int x = (c >= off) ? tmp[c - off] : 0;
        __syncthreads();
        tmp[c] += x;
        __syncthreads();
    }
    int running = tmp[c] - total;
    #pragma unroll
    for (int bk = 0; bk < NSBLK; bk++) {
        g_bbase[bk][c] = running;
        running += g_bhist[bk][c];
    }
}

__global__ void sort_scatter_kernel(const float* __restrict__ tpl)
{
    __shared__ int lh[256];
    __shared__ int lbase[256];
    const int tid = threadIdx.x;
    if (tid < 256) {
        lh[tid] = 0;
        lbase[tid] = g_bbase[blockIdx.x][tid];
    }
    __syncthreads();
    int p = blockIdx.x * 512 + tid;
    if (p < NPTS) {
        float2 P = ((const float2*)tpl)[p];
        int c = cell_of(P);
        int idx = lbase[c] + atomicAdd(&lh[c], 1);
        g_order[idx] = p;
        g_tps[idx] = P;
    }
}

// ============================================================================
// Encoder layers 1-4, split into 2 halo-free row-halves per batch.
// Grid 2*BATCH, 512 threads. k=2,s=2 convs never cross the half boundary.
// smem: OBSh[2][32][64]=4096, A1h[4][16][32]=2048, A2h[8][8][16]=1024,
//       A3h[16][4][8]=512  (7680 floats = 30 KB)
// ============================================================================
__global__ __launch_bounds__(512)
void enc_kernel(const float* __restrict__ obs,
    const float* __restrict__ w1, const float* __restrict__ b1,
    const float* __restrict__ w2, const float* __restrict__ b2,
    const float* __restrict__ w3, const float* __restrict__ b3,
    const float* __restrict__ w4, const float* __restrict__ b4)
{
    __shared__ float OB[4096];
    __shared__ float A1[2048];
    __shared__ float A2[1024];
    __shared__ float A3[512];
    const int b = blockIdx.x >> 1;
    const int h = blockIdx.x & 1;
    const int tid = threadIdx.x;

    // stage obs rows [h*32, h*32+32) of both channels (1024 float4)
    {
        const float4* src = (const float4*)obs;
        float4* dst = (float4*)OB;
        #pragma unroll
        for (int it = 0; it < 2; it++) {
            int i = tid + it * 512;                 // i < 1024
            int ci = i >> 9, row = (i >> 4) & 31, c4 = i & 15;
            dst[i] = src[b*2048 + ci*1024 + (h*32 + row)*16 + c4];
        }
    }
    __syncthreads();

    // layer1 half: [2,32,64] -> [4,16,32]  (2048 outputs)
    #pragma unroll
    for (int it = 0; it < 4; it++) {
        int n = tid + it * 512;
        int o = n >> 9, r = (n >> 5) & 15, c = n & 31;
        float s = b1[o];
        #pragma unroll
        for (int ci = 0; ci < 2; ci++)
            #pragma unroll
            for (int m = 0; m < 2; m++) {
                float2 xv = ((const float2*)&OB[ci*2048 + (2*r+m)*64])[c];
                s += xv.x * w1[o*8 + ci*4 + m*2] + xv.y * w1[o*8 + ci*4 + m*2 + 1];
            }
        A1[n] = tanh_fast(s);
    }
    __syncthreads();
    // layer2 half: -> [8,8,16]  (1024)
    #pragma unroll
    for (int it = 0; it < 2; it++) {
        int n = tid + it * 512;
        int o = n >> 7, r = (n >> 4) & 7, c = n & 15;
        float s = b2[o];
        #pragma unroll
        for (int ci = 0; ci < 4; ci++)
            #pragma unroll
            for (int m = 0; m < 2; m++) {
                float2 xv = ((const float2*)&A1[ci*512 + (2*r+m)*32])[c];
                s += xv.x * w2[o*16 + ci*4 + m*2] + xv.y * w2[o*16 + ci*4 + m*2 + 1];
            }
        A2[n] = tanh_fast(s);
    }
    __syncthreads();
    // layer3 half: -> [16,4,8]  (512)
    {
        int n = tid;
        int o = n >> 5, r = (n >> 3) & 3, c = n & 7;
        float s = b3[o];
        #pragma unroll
        for (int ci = 0; ci < 8; ci++)
            #pragma unroll
            for (int m = 0; m < 2; m++) {
                float2 xv = ((const float2*)&A2[ci*128 + (2*r+m)*16])[c];
                s += xv.x * w3[o*32 + ci*4 + m*2] + xv.y * w3[o*32 + ci*4 + m*2 + 1];
            }
        A3[n] = tanh_fast(s);
    }
    __syncthreads();
    // layer4 half: -> [16,2,4]  (128) -> global g_a4[b][o][h*2+r][c]
    if (tid < 128) {
        int o = tid >> 3, r = (tid >> 2) & 1, c = tid & 3;
        float s = b4[o];
        #pragma unroll
        for (int ci = 0; ci < 16; ci++)
            #pragma unroll
            for (int m = 0; m < 2; m++) {
                float2 xv = ((const float2*)&A3[ci*32 + (2*r+m)*8])[c];
                s += xv.x * w4[o*64 + ci*4 + m*2] + xv.y * w4[o*64 + ci*4 + m*2 + 1];
            }
        g_a4[b*256 + o*16 + (h*2 + r)*4 + c] = tanh_fast(s);
    }
}

// ============================================================================
// Linear + decoder + coefficient build, one block per (b, t). Grid 2560, 256 thr.
// ============================================================================
__global__ __launch_bounds__(256)
void dec_kernel(const float* __restrict__ lw, const float* __restrict__ lb,
    const float* __restrict__ dlw,
    const float* __restrict__ dw1, const float* __restrict__ dw2,
    const float* __restrict__ dw3)
{
    __shared__ float RED[80];
    __shared__ float Z[LAT];
    __shared__ float H[64];
    __shared__ float O1[128];
    __shared__ float O2[256];
    __shared__ float VF[512];
    const int bt = blockIdx.x;
    const int b = bt / TSTEPS, t = bt - b * TSTEPS;
    const float scale = 0.1f * (float)(t + 1);
    const int tid = threadIdx.x;
    const float* a4 = g_a4 + b * 256;

    if (tid < 80) {
        int l = tid >> 3, seg = tid & 7;
        float s = 0.f;
        #pragma unroll
        for (int k = 0; k < 32; k++)
            s += a4[seg*32 + k] * lw[l*256 + seg*32 + k];
        RED[tid] = s;
    }
    __syncthreads();
    if (tid < LAT) {
        float s = lb[tid];
        #pragma unroll
        for (int k = 0; k < 8; k++) s += RED[tid*8 + k];
        Z[tid] = s;
    }
    __syncthreads();
    if (tid < 64) {
        float s = 0.f;
        #pragma unroll
        for (int l = 0; l < LAT; l++) s += Z[l] * dlw[tid*LAT + l];
        H[tid] = tanh_fast(scale * s);
    }
    __syncthreads();
    // convT1: 16->8, [2,2]->[4,4]  (128)
    if (tid < 128) {
        int o = tid >> 4, p = (tid >> 2) & 3, q = tid & 3;
        float s = 0.f;
        #pragma unroll
        for (int c = 0; c < 16; c++)
            s += H[c*4 + (p>>1)*2 + (q>>1)]
               * dw1[c*32 + o*4 + (1-(p&1))*2 + (1-(q&1))];
        O1[o*16 + p*4 + q] = tanh_fast(s);
    }
    __syncthreads();
    // convT2: 8->4, [4,4]->[8,8]  (256)
    {
        int o = tid >> 6, p = (tid >> 3) & 7, q = tid & 7;
        float s = 0.f;
        #pragma unroll
        for (int c = 0; c < 8; c++)
            s += O1[c*16 + (p>>1)*4 + (q>>1)]
               * dw2[c*16 + o*4 + (1-(p&1))*2 + (1-(q&1))];
        O2[o*64 + p*8 + q] = tanh_fast(s);
    }
    __syncthreads();
    // convT3: 4->2, [8,8]->[16,16]  (512), no tanh
    #pragma unroll
    for (int it = 0; it < 2; it++) {
        int n = tid + it * 256;
        int o = n >> 8, p = (n >> 4) & 15, q = n & 15;
        float s = 0.f;
        #pragma unroll
        for (int c = 0; c < 4; c++)
            s += O2[c*64 + (p>>1)*8 + (q>>1)]
               * dw3[c*8 + o*4 + (1-(p&1))*2 + (1-(q&1))];
        VF[o*256 + p*16 + q] = s;
    }
    __syncthreads();
    // coefficient table for this (b,t), prescaled by 3*dt
    float* cc = g_coef + (size_t)b * COEF_PER_BATCH + t * 2048;
    const float Sc = 0.3f;
    {
        int cell = tid;
        int i = cell >> 4, j = cell & 15;
        int i2 = min(i + 1, 15), j2 = min(j + 1, 15);
        float v00x = VF[i*16 + j],    v00y = VF[256 + i*16 + j];
        float v10x = VF[i2*16 + j],   v10y = VF[256 + i2*16 + j];
        float v01x = VF[i*16 + j2],   v01y = VF[256 + i*16 + j2];
        float v11x = VF[i2*16 + j2],  v11y = VF[256 + i2*16 + j2];
        float4 ca = make_float4(Sc*v00x, Sc*v00y, Sc*(v10x - v00x), Sc*(v10y - v00y));
        float4 cb = make_float4(Sc*(v01x - v00x), Sc*(v01y - v00y),
                                Sc*(v11x - v01x - v10x + v00x),
                                Sc*(v11y - v01y - v10y + v00y));
        float4* d = (float4*)(cc + cell * 8);
        d[0] = ca; d[1] = cb;
    }
}

// ============================================================================
// Integration, 2-phase time split: 40 KB coef table per phase -> 3 blocks/SM
// (48 warps). Point state (8 pts/thread) persists in registers across phases.
// ============================================================================
__device__ __forceinline__ void euler_step(const float* sc, int tt,
                                           float& u, float& v)
{
    float uf = floorf(u), vf = floorf(v);
    float fu = u - uf,    fv = v - vf;
    float idxf = fminf(fmaxf(uf * 16.0f + vf, 0.0f), 255.0f);
    int idx = __float2int_rz(idxf);
    const float4* c = (const float4*)&sc[(tt << 11) + (idx << 3)];
    float4 ca = c[0];
    float4 cb = c[1];
    float fufv = fu * fv;
    u += ca.x + fu*ca.z + fv*cb.x + fufv*cb.z;
    v += ca.y + fu*ca.w + fv*cb.y + fufv*cb.w;
}

__global__ __launch_bounds__(ITHREADS, 3)
void integrate_kernel(float* __restrict__ out)
{
    extern __shared__ float sc[];     // HALF_COEF floats = 40 KB
    const int b   = blockIdx.x / BPB;
    const int blk = blockIdx.x % BPB;
    const int tid = threadIdx.x;
    const int base = blk * PPB;

    // load my 8 points into registers (grid coords); k=7 partial
    float us[8], vs[8];
    #pragma unroll
    for (int k = 0; k < 8; k++) {
        int off = tid + k * ITHREADS;
        if (off < PPB) {
            float2 P = g_tps[base + off];
            us[k] = (P.x + 2.5f) * 3.0f;
            vs[k] = (P.y + 2.5f) * 3.0f;
        } else { us[k] = 0.f; vs[k] = 0.f; }
    }

    #pragma unroll
    for (int ph = 0; ph < 2; ph++) {
        __syncthreads();   // prior phase's reads complete before overwrite
        const float4* src = (const float4*)(g_coef + (size_t)b * COEF_PER_BATCH
                                            + ph * HALF_COEF);
        float4* dst = (float4*)sc;
        #pragma unroll
        for (int i = 0; i < HALF_COEF / 4 / ITHREADS; i++)
            dst[tid + i * ITHREADS] = src[tid + i * ITHREADS];
        __syncthreads();
        #pragma unroll
        for (int kk = 0; kk < 4; kk++) {
            #pragma unroll
            for (int tt = 0; tt < TSTEPS / 2; tt++) {
                euler_step(sc, tt, us[2*kk],   vs[2*kk]);
                euler_step(sc, tt, us[2*kk+1], vs[2*kk+1]);
            }
        }
    }

    float2* op2 = (float2*)out + (size_t)b * NPTS;
    #pragma unroll
    for (int k = 0; k < 8; k++) {
        int off = tid + k * ITHREADS;
        if (off < PPB) {
            int po = g_order[base + off];
            op2[po] = make_float2(us[k] * (1.0f/3.0f) - 2.5f,
                                  vs[k] * (1.0f/3.0f) - 2.5f);
        }
    }
}

// ============================================================================
extern "C" void kernel_launch(void* const* d_in, const int* in_sizes, int n_in,
                              void* d_out, int out_size)
{
    const float* obs   = (const float*)d_in[0];
    const float* tpl   = (const float*)d_in[1];
    const float* ew1   = (const float*)d_in[2];
    const float* eb1   = (const float*)d_in[3];
    const float* ew2   = (const float*)d_in[4];
    const float* eb2   = (const float*)d_in[5];
    const float* ew3   = (const float*)d_in[6];
    const float* eb3   = (const float*)d_in[7];
    const float* ew4   = (const float*)d_in[8];
    const float* eb4   = (const float*)d_in[9];
    const float* elw   = (const float*)d_in[10];
    const float* elb   = (const float*)d_in[11];
    const float* dlw   = (const float*)d_in[12];
    const float* dw1   = (const float*)d_in[13];
    const float* dw2   = (const float*)d_in[14];
    const float* dw3   = (const float*)d_in[15];
    float* out = (float*)d_out;

    sort_count_kernel<<<NSBLK, 512>>>(tpl);
    sort_scan_kernel<<<1, 256>>>();
    sort_scatter_kernel<<<NSBLK, 512>>>(tpl);
    enc_kernel<<<BATCH * 2, 512>>>(obs, ew1, eb1, ew2, eb2, ew3, eb3, ew4, eb4);
    dec_kernel<<<BATCH * TSTEPS, 256>>>(elw, elb, dlw, dw1, dw2, dw3);
    integrate_kernel<<<BATCH * BPB, ITHREADS, HALF_COEF * 4>>>(out);
}